// round 5
// baseline (speedup 1.0000x reference)
#include <cuda_runtime.h>
#include <cstdint>

// RecallLoss: input [N=8, C=21, H=512, W=512] f32, target [N, H, W] int64 (or
// int32 — auto-detected). loss = 1 - mean_{n,c} (tp+eps)/(tt+eps).
//
// Single fused kernel, barrier-free mainloop: per-warp packed counters over
// all 168 (n,c) bins, so chunk iterations need no __syncthreads and warps
// keep LDGs in flight continuously. One end-of-block reduce + last-block
// epilogue computes the scalar and resets state for graph replay.

#define SMOOTH 1e-5f

constexpr int N_IMG  = 8;
constexpr int C_CLS  = 21;
constexpr int HW     = 512 * 512;          // 262144 positions per image
constexpr int HW4    = HW / 4;             // 65536 float4-chunks per image
constexpr int NC     = N_IMG * C_CLS;      // 168 bins
constexpr int TPB    = 256;
constexpr int GRID   = 1024;
constexpr int NTHREADS = GRID * TPB;       // 262144
constexpr int NCHUNK = N_IMG * HW4;        // 524288 = 2 * NTHREADS
constexpr int ITERS  = NCHUNK / NTHREADS;  // 2
constexpr int NWARP  = TPB / 32;           // 8

// Zero-initialized at module load; finishing block re-zeroes after each
// launch so every graph replay starts clean.
__device__ int g_tp[NC];
__device__ int g_tt[NC];
__device__ unsigned int g_arrive;

__global__ __launch_bounds__(TPB) void recall_fused_kernel(
    const float* __restrict__ inp, const void* __restrict__ tgt_raw,
    float* __restrict__ out)
{
    // Per-warp packed counters: bits[15:0]=tt, bits[31:16]=tp.
    // Max per bin per warp = ITERS*32*4 = 256 << 65536.
    __shared__ unsigned int s_cnt[NWARP][NC];
    __shared__ int s_is64;
    __shared__ float s_red[NWARP];

    const int wid = threadIdx.x >> 5;
    const int lid = threadIdx.x & 31;
    #pragma unroll
    for (int k = lid; k < NC; k += 32) s_cnt[wid][k] = 0;

    // dtype detect: int64 targets in [0,21) have all-zero odd 32-bit words;
    // for int32 the chance 16 specific odd words are all 0 is (1/21)^16 ~ 0.
    if (threadIdx.x == 0) {
        const int* w = (const int*)tgt_raw;
        int is64 = 1;
        #pragma unroll
        for (int k = 0; k < 16; k++) is64 &= (w[2 * k + 1] == 0);
        s_is64 = is64;
    }
    __syncthreads();
    const int is64 = s_is64;
    const int gtid = blockIdx.x * TPB + threadIdx.x;
    unsigned int* const cnt = s_cnt[wid];

    // Barrier-free mainloop. unroll 1 keeps a single body instance so the
    // register footprint (and thus occupancy) matches the 1-chunk kernel.
    #pragma unroll 1
    for (int it = 0; it < ITERS; it++) {
        const int ci = gtid + it * NTHREADS;
        const int n  = ci >> 16;                       // HW4 = 65536
        const long long l0 = (long long)(ci & (HW4 - 1)) * 4;
        const float* base = inp + (long long)n * C_CLS * HW + l0;

        // Channel 0 seeds; strict > keeps first max index (jnp.argmax ties).
        // __ldcs: data is touched exactly once — evict-first.
        float4 v = __ldcs(reinterpret_cast<const float4*>(base));
        float m0 = v.x, m1 = v.y, m2 = v.z, m3 = v.w;
        int   i0 = 0,  i1 = 0,  i2 = 0,  i3 = 0;

        #pragma unroll
        for (int c = 1; c < C_CLS; c++) {
            float4 u = __ldcs(reinterpret_cast<const float4*>(base + (long long)c * HW));
            if (u.x > m0) { m0 = u.x; i0 = c; }
            if (u.y > m1) { m1 = u.y; i1 = c; }
            if (u.z > m2) { m2 = u.z; i2 = c; }
            if (u.w > m3) { m3 = u.w; i3 = c; }
        }

        int t0, t1, t2, t3;
        if (is64) {
            const long long* tp = (const long long*)tgt_raw + (long long)n * HW + l0;
            longlong2 a = __ldcs(reinterpret_cast<const longlong2*>(tp));
            longlong2 b = __ldcs(reinterpret_cast<const longlong2*>(tp + 2));
            t0 = (int)a.x; t1 = (int)a.y; t2 = (int)b.x; t3 = (int)b.y;
        } else {
            const int* tp = (const int*)tgt_raw + (long long)n * HW + l0;
            int4 a = __ldcs(reinterpret_cast<const int4*>(tp));
            t0 = a.x; t1 = a.y; t2 = a.z; t3 = a.w;
        }

        const int nb = n * C_CLS;
        atomicAdd(&cnt[nb + t0], 1u + (i0 == t0 ? 0x10000u : 0u));
        atomicAdd(&cnt[nb + t1], 1u + (i1 == t1 ? 0x10000u : 0u));
        atomicAdd(&cnt[nb + t2], 1u + (i2 == t2 ? 0x10000u : 0u));
        atomicAdd(&cnt[nb + t3], 1u + (i3 == t3 ? 0x10000u : 0u));
    }

    __syncthreads();

    // Block reduce: 168 bins, sum 8 warp rows, one global atomic pair each.
    if (threadIdx.x < NC) {
        unsigned int a = 0;
        #pragma unroll
        for (int w = 0; w < NWARP; w++) a += s_cnt[w][threadIdx.x];
        atomicAdd(&g_tt[threadIdx.x], (int)(a & 0xFFFFu));
        atomicAdd(&g_tp[threadIdx.x], (int)(a >> 16));
    }

    // ---- last-block epilogue -------------------------------------------
    __shared__ int s_last;
    __threadfence();   // release this block's counter contributions
    if (threadIdx.x == 0) {
        unsigned int old = atomicAdd(&g_arrive, 1u);
        s_last = (old == (unsigned int)(GRID - 1));
    }
    __syncthreads();
    if (!s_last) return;

    __threadfence();   // acquire all blocks' contributions
    const int i = threadIdx.x;
    float r = 0.0f;
    if (i < NC) {
        r = ((float)g_tp[i] + SMOOTH) / ((float)g_tt[i] + SMOOTH);
    }
    #pragma unroll
    for (int o = 16; o > 0; o >>= 1) r += __shfl_down_sync(0xffffffffu, r, o);
    if (lid == 0) s_red[wid] = r;
    __syncthreads();
    if (i == 0) {
        float s = 0.0f;
        #pragma unroll
        for (int w = 0; w < NWARP; w++) s += s_red[w];
        out[0] = 1.0f - s / (float)NC;
    }

    // Reset state for the next graph replay.
    if (i < NC) { g_tp[i] = 0; g_tt[i] = 0; }
    if (i == 0) g_arrive = 0u;
}

extern "C" void kernel_launch(void* const* d_in, const int* in_sizes, int n_in,
                              void* d_out, int out_size) {
    const float* inp = (const float*)d_in[0];
    const void*  tgt = d_in[1];
    float* out = (float*)d_out;

    recall_fused_kernel<<<GRID, TPB>>>(inp, tgt, out);
}

// round 6
// speedup vs baseline: 1.0052x; 1.0052x over previous
#include <cuda_runtime.h>
#include <cstdint>

// RecallLoss: input [N=8, C=21, H=512, W=512] f32, target [N, H, W] int64 (or
// int32 — auto-detected). loss = 1 - mean_{n,c} (tp+eps)/(tt+eps).
//
// Single fused kernel (R3 shape) with ZERO hot-path atomics: per-position
// counts are warp-aggregated via __match_any_sync, and the unique per-class
// leader lane does a plain read-modify-write on the warp-private smem counter
// row. Atomics previously saturated the LSU/MIO pipe (ATOMS spread ~2cyc/lane
// * 21-way * 8 per chunk), capping DRAM at ~65% across all launch shapes.

#define SMOOTH 1e-5f

constexpr int N_IMG  = 8;
constexpr int C_CLS  = 21;
constexpr int HW     = 512 * 512;       // 262144 positions per image
constexpr int NC     = N_IMG * C_CLS;   // 168 bins
constexpr int TPB    = 256;
constexpr int IPT    = 4;               // positions per thread (float4)
constexpr int BLKS_PER_IMG = HW / (TPB * IPT);   // 256
constexpr int GRID   = N_IMG * BLKS_PER_IMG;     // 2048
constexpr int NWARP  = TPB / 32;        // 8

// Zero-initialized at module load; the finishing block re-zeroes after each
// launch so every graph replay starts clean.
__device__ int g_tp[NC];
__device__ int g_tt[NC];
__device__ unsigned int g_arrive;

// Warp-aggregated counter update for one position: counts lanes sharing this
// lane's class (tt) and those that also matched argmax (tp), packed tp<<16|tt.
// The lowest lane of each class group does a plain RMW — the counter row is
// warp-private and distinct classes hit distinct addresses, so no atomic is
// needed; the 4 per-chunk calls are ordered by program order within the warp.
__device__ __forceinline__ void warp_count(
    unsigned int* __restrict__ cnt, int t, int pred_match, int lid)
{
    unsigned int grp = __match_any_sync(0xffffffffu, t);
    unsigned int mb  = __ballot_sync(0xffffffffu, pred_match);
    unsigned int add = __popc(grp) + (__popc(grp & mb) << 16);
    if ((grp & ((1u << lid) - 1u)) == 0u)   // leader: lowest lane of group
        cnt[t] += add;
}

__global__ __launch_bounds__(TPB) void recall_fused_kernel(
    const float* __restrict__ inp, const void* __restrict__ tgt_raw,
    float* __restrict__ out)
{
    // Per-warp packed counters: bits[15:0]=tt, bits[31:16]=tp.
    // Max per bin per warp = 32 lanes * 4 positions = 128 << 65536.
    __shared__ unsigned int s_cnt[NWARP][C_CLS];
    __shared__ int s_is64;
    __shared__ float s_red[NWARP];

    const int wid = threadIdx.x >> 5;
    const int lid = threadIdx.x & 31;
    if (lid < C_CLS) s_cnt[wid][lid] = 0;

    // dtype detect: int64 targets in [0,21) have all-zero odd 32-bit words;
    // for int32 the chance 16 specific odd words are all 0 is (1/21)^16 ~ 0.
    if (threadIdx.x == 0) {
        const int* w = (const int*)tgt_raw;
        int is64 = 1;
        #pragma unroll
        for (int k = 0; k < 16; k++) is64 &= (w[2 * k + 1] == 0);
        s_is64 = is64;
    }
    __syncthreads();

    const int n   = blockIdx.x >> 8;         // BLKS_PER_IMG = 256
    const int blk = blockIdx.x & 255;
    const int l0  = blk * (TPB * IPT) + threadIdx.x * IPT;   // < 2^18

    // All-32-bit offsets: max element index 8*21*262144 = 44M < 2^31.
    const float* base = inp + (n * C_CLS * HW + l0);

    // Channel 0 seeds; strict > keeps first max index (jnp.argmax ties).
    // __ldcs: single-touch streaming data, evict-first.
    float4 v = __ldcs(reinterpret_cast<const float4*>(base));
    float m0 = v.x, m1 = v.y, m2 = v.z, m3 = v.w;
    int   i0 = 0,  i1 = 0,  i2 = 0,  i3 = 0;

    #pragma unroll
    for (int c = 1; c < C_CLS; c++) {
        float4 u = __ldcs(reinterpret_cast<const float4*>(base + c * HW));
        if (u.x > m0) { m0 = u.x; i0 = c; }
        if (u.y > m1) { m1 = u.y; i1 = c; }
        if (u.z > m2) { m2 = u.z; i2 = c; }
        if (u.w > m3) { m3 = u.w; i3 = c; }
    }

    int t0, t1, t2, t3;
    if (s_is64) {
        const long long* tp = (const long long*)tgt_raw + (n * HW + l0);
        longlong2 a = __ldcs(reinterpret_cast<const longlong2*>(tp));
        longlong2 b = __ldcs(reinterpret_cast<const longlong2*>(tp + 2));
        t0 = (int)a.x; t1 = (int)a.y; t2 = (int)b.x; t3 = (int)b.y;
    } else {
        const int* tp = (const int*)tgt_raw + (n * HW + l0);
        int4 a = __ldcs(reinterpret_cast<const int4*>(tp));
        t0 = a.x; t1 = a.y; t2 = a.z; t3 = a.w;
    }

    unsigned int* const cnt = s_cnt[wid];
    warp_count(cnt, t0, i0 == t0, lid);
    warp_count(cnt, t1, i1 == t1, lid);
    warp_count(cnt, t2, i2 == t2, lid);
    warp_count(cnt, t3, i3 == t3, lid);

    __syncthreads();

    // Block reduce: 21 bins, sum 8 warp rows, one global atomic pair each.
    if (threadIdx.x < C_CLS) {
        unsigned int a = 0;
        #pragma unroll
        for (int w = 0; w < NWARP; w++) a += s_cnt[w][threadIdx.x];
        atomicAdd(&g_tt[n * C_CLS + threadIdx.x], (int)(a & 0xFFFFu));
        atomicAdd(&g_tp[n * C_CLS + threadIdx.x], (int)(a >> 16));
    }

    // ---- last-block epilogue -------------------------------------------
    __shared__ int s_last;
    __threadfence();   // release this block's counter contributions
    if (threadIdx.x == 0) {
        unsigned int old = atomicAdd(&g_arrive, 1u);
        s_last = (old == (unsigned int)(GRID - 1));
    }
    __syncthreads();
    if (!s_last) return;

    __threadfence();   // acquire all blocks' contributions
    const int i = threadIdx.x;
    float r = 0.0f;
    if (i < NC) {
        r = ((float)g_tp[i] + SMOOTH) / ((float)g_tt[i] + SMOOTH);
    }
    #pragma unroll
    for (int o = 16; o > 0; o >>= 1) r += __shfl_down_sync(0xffffffffu, r, o);
    if (lid == 0) s_red[wid] = r;
    __syncthreads();
    if (i == 0) {
        float s = 0.0f;
        #pragma unroll
        for (int w = 0; w < NWARP; w++) s += s_red[w];
        out[0] = 1.0f - s / (float)NC;
    }

    // Reset state for the next graph replay.
    if (i < NC) { g_tp[i] = 0; g_tt[i] = 0; }
    if (i == 0) g_arrive = 0u;
}

extern "C" void kernel_launch(void* const* d_in, const int* in_sizes, int n_in,
                              void* d_out, int out_size) {
    const float* inp = (const float*)d_in[0];
    const void*  tgt = d_in[1];
    float* out = (float*)d_out;

    recall_fused_kernel<<<GRID, TPB>>>(inp, tgt, out);
}